// round 10
// baseline (speedup 1.0000x reference)
#include <cuda_runtime.h>
#include <cuda_bf16.h>

#define NROW 8192
#define DIM  256
#define NB   64                  // NROW / 128
#define NTILES (NB * (NB + 1) / 2)   // 2080
#define CORRF (256.0f/255.0f)
#define KCONST (CORRF/128.0f)
#define HALF_BYTES 32768         // 128 rows x 128 bf16 (256B), swizzled
#define HALF_U4 (HALF_BYTES/16)  // 2048
#define NTHREADS 1024

// ---------------- scratch ----------------
// layout: per 128-row block b, two contiguous 32KB halves (k<128, k>=128)
__device__ uint4  d_ebf4[NB * 2 * HALF_U4];
__device__ float4 d_rp[NROW];    // {V, 16*m, 1/V, label bits}

struct Acc {
    double pos_sum, neg_sum, reg_sum;
    unsigned long long pos_cnt, neg_cnt;
    unsigned done;
};
__device__ Acc d_acc;

__device__ __forceinline__ unsigned smem_u32(const void* p) {
    unsigned a;
    asm("{ .reg .u64 t; cvta.to.shared.u64 t, %1; cvt.u32.u64 %0, t; }" : "=r"(a) : "l"(p));
    return a;
}

#define LDSM_X4(r0, r1, r2, r3, a) \
    asm volatile("ldmatrix.sync.aligned.m8n8.x4.shared.b16 {%0,%1,%2,%3}, [%4];" \
        : "=r"(r0), "=r"(r1), "=r"(r2), "=r"(r3) : "r"(a))

#define MMA_BF16(d, a0, a1, a2, a3, b0, b1) \
    asm volatile("mma.sync.aligned.m16n8k16.row.col.f32.bf16.bf16.f32 " \
        "{%0,%1,%2,%3}, {%4,%5,%6,%7}, {%8,%9}, {%0,%1,%2,%3};" \
        : "+f"((d)[0]), "+f"((d)[1]), "+f"((d)[2]), "+f"((d)[3]) \
        : "r"(a0), "r"(a1), "r"(a2), "r"(a3), "r"(b0), "r"(b1))

__device__ __forceinline__ void copy_half_async(unsigned sdst, const uint4* g, int t) {
    #pragma unroll
    for (int i = 0; i < 2; i++) {
        int idx = t + i * NTHREADS;
        asm volatile("cp.async.cg.shared.global [%0], [%1], 16;"
            :: "r"(sdst + idx * 16), "l"(g + idx));
    }
}
#define CP_COMMIT()  asm volatile("cp.async.commit_group;" ::: "memory")
#define CP_WAIT(n)   asm volatile("cp.async.wait_group %0;" :: "n"(n) : "memory")

// ---------------- precompute: normalize, stats, bf16 swizzled store ----------------
__global__ void precompute_kernel(const float* __restrict__ x,
                                  const long long* __restrict__ lab) {
    int row = blockIdx.x;
    int t = threadIdx.x;                 // feature index, blockDim = 256
    float v = x[row * DIM + t];

    float ss = v * v;
    #pragma unroll
    for (int o = 16; o; o >>= 1) ss += __shfl_xor_sync(0xffffffffu, ss, o);
    __shared__ float red[8];
    if ((t & 31) == 0) red[t >> 5] = ss;
    __syncthreads();
    float tot = red[0] + red[1] + red[2] + red[3] + red[4] + red[5] + red[6] + red[7];

    float norm = sqrtf(tot);
    float e = v / norm;

    __shared__ __nv_bfloat16 sh_e[DIM];
    sh_e[t] = __float2bfloat16(e);

    float s1 = e, s2 = e * e;
    #pragma unroll
    for (int o = 16; o; o >>= 1) {
        s1 += __shfl_xor_sync(0xffffffffu, s1, o);
        s2 += __shfl_xor_sync(0xffffffffu, s2, o);
    }
    __shared__ float red1[8], red2[8];
    if ((t & 31) == 0) { red1[t >> 5] = s1; red2[t >> 5] = s2; }
    __syncthreads();

    if (t < 32) {
        int c = t;                       // global 16B chunk index 0..31
        int k0 = c * 8;
        unsigned w0 = (unsigned)__bfloat16_as_ushort(sh_e[k0 + 0]) | ((unsigned)__bfloat16_as_ushort(sh_e[k0 + 1]) << 16);
        unsigned w1 = (unsigned)__bfloat16_as_ushort(sh_e[k0 + 2]) | ((unsigned)__bfloat16_as_ushort(sh_e[k0 + 3]) << 16);
        unsigned w2 = (unsigned)__bfloat16_as_ushort(sh_e[k0 + 4]) | ((unsigned)__bfloat16_as_ushort(sh_e[k0 + 5]) << 16);
        unsigned w3 = (unsigned)__bfloat16_as_ushort(sh_e[k0 + 6]) | ((unsigned)__bfloat16_as_ushort(sh_e[k0 + 7]) << 16);
        uint4 val; val.x = w0; val.y = w1; val.z = w2; val.w = w3;
        int rb = row & 127;
        int h  = c >> 4;                 // K-half
        int c2 = c & 15;                 // chunk within half (16 per 256B row)
        size_t base = ((size_t)(row >> 7) * 2 + h) * HALF_BYTES;
        unsigned off = (unsigned)rb * 256u + (unsigned)((c2 ^ (rb & 7)) << 4);
        *(uint4*)((char*)d_ebf4 + base + off) = val;
    }

    if (t == 0) {
        float sum_e = 0.f, sum_e2 = 0.f;
        #pragma unroll
        for (int w = 0; w < 8; w++) { sum_e += red1[w]; sum_e2 += red2[w]; }
        float m = sum_e * (1.0f / DIM);
        float s = sum_e2 * (1.0f / DIM);
        float V = CORRF * (s - m * m);
        d_rp[row] = make_float4(V, 16.0f * m, 1.0f / V, __int_as_float((int)lab[row]));
        atomicAdd(&d_acc.reg_sum, (double)fabsf(sum_e));
    }
}

// ---------------- pair kernel (1024 threads, warp = 16x32 sub-tile) ----------------
// dyn smem: [0..2048) j-params, [4096..) A0, B0, A1, B1 (32KB each)
#define SM_JP 0
#define SM_A0 4096
#define SM_B0 (SM_A0 + HALF_BYTES)
#define SM_A1 (SM_B0 + HALF_BYTES)
#define SM_B1 (SM_A1 + HALF_BYTES)
#define SM_TOTAL (SM_B1 + HALF_BYTES)

struct Stage { unsigned a, b; };

__global__ __launch_bounds__(NTHREADS, 1) void pair_kernel(float* __restrict__ out) {
    // triangular linear index -> (bi, bj), bj >= bi
    int li = blockIdx.x;
    int bi = (int)((2.0f * NB + 1.0f - sqrtf((2.0f * NB + 1.0f) * (2.0f * NB + 1.0f) - 8.0f * (float)li)) * 0.5f);
    while (NB * bi - bi * (bi - 1) / 2 > li) bi--;
    while (NB * (bi + 1) - (bi + 1) * bi / 2 <= li) bi++;
    int bj = bi + (li - (NB * bi - bi * (bi - 1) / 2));
    bool diag = (bi == bj);

    extern __shared__ char smem[];
    int t = threadIdx.x, w = t >> 5, l = t & 31;
    int wrow = w & 7;          // M strip (16 rows)
    int wcol = w >> 3;         // N quarter (32 cols)
    unsigned sb0 = smem_u32(smem);

    const uint4* Abase = d_ebf4 + (size_t)(bi * 2) * HALF_U4;
    const uint4* Bbase = d_ebf4 + (size_t)(bj * 2) * HALF_U4;

    // pipeline: stage0 <- half0, stage1 <- half1
    copy_half_async(sb0 + SM_A0, Abase, t);
    if (!diag) copy_half_async(sb0 + SM_B0, Bbase, t);
    CP_COMMIT();
    copy_half_async(sb0 + SM_A1, Abase + HALF_U4, t);
    if (!diag) copy_half_async(sb0 + SM_B1, Bbase + HALF_U4, t);
    CP_COMMIT();

    if (t < 128) ((float4*)(smem + SM_JP))[t] = d_rp[bj * 128 + t];

    // per-lane ldmatrix addressing
    int i0 = wrow * 16;
    int rA = i0 + (l & 7) + (l & 8);
    int rxA = rA & 7;
    int hi = l >> 4;
    int rBoff = (l & 7) + (l & 8);
    int rB[2], rxB[2];
    #pragma unroll
    for (int nb = 0; nb < 2; nb++) {
        rB[nb] = wcol * 32 + nb * 16 + rBoff;
        rxB[nb] = rB[nb] & 7;
    }

    float acc[4][4];
    #pragma unroll
    for (int i = 0; i < 4; i++)
        #pragma unroll
        for (int j = 0; j < 4; j++) acc[i][j] = 0.f;

    Stage st[2];
    st[0].a = sb0 + SM_A0; st[0].b = diag ? (sb0 + SM_A0) : (sb0 + SM_B0);
    st[1].a = sb0 + SM_A1; st[1].b = diag ? (sb0 + SM_A1) : (sb0 + SM_B1);

    #pragma unroll
    for (int s = 0; s < 2; s++) {
        if (s == 0) CP_WAIT(1); else CP_WAIT(0);
        __syncthreads();
        unsigned aRow = st[s].a + (unsigned)rA * 256u;
        unsigned bRow[2];
        #pragma unroll
        for (int nb = 0; nb < 2; nb++) bRow[nb] = st[s].b + (unsigned)rB[nb] * 256u;

        #pragma unroll
        for (int ks = 0; ks < 8; ks++) {
            int cc = 2 * ks + hi;
            unsigned a0, a1, a2, a3;
            LDSM_X4(a0, a1, a2, a3, aRow + (unsigned)((cc ^ rxA) << 4));
            #pragma unroll
            for (int nb = 0; nb < 2; nb++) {
                unsigned m0, m1, m2, m3;
                LDSM_X4(m0, m1, m2, m3, bRow[nb] + (unsigned)((cc ^ rxB[nb]) << 4));
                MMA_BF16(acc[2 * nb],     a0, a1, a2, a3, m0, m2);
                MMA_BF16(acc[2 * nb + 1], a0, a1, a2, a3, m1, m3);
            }
        }
    }

    // ---- fused epilogue ----
    int r0 = i0 + (l >> 2);
    int gi0 = bi * 128 + r0;
    float4 ipa = d_rp[gi0];
    float4 ipb = d_rp[gi0 + 8];
    const float4* jp = (const float4*)(smem + SM_JP);
    int jlo = (l & 3) * 2;

    float ps = 0.f, ns = 0.f;
    int pc = 0, nc = 0;

    #pragma unroll
    for (int tn = 0; tn < 4; tn++) {
        #pragma unroll
        for (int v = 0; v < 4; v++) {
            int cj = wcol * 32 + tn * 8 + jlo + (v & 1);
            int ri = (v < 2) ? r0 : (r0 + 8);
            if (diag && ri >= cj) continue;
            float4 ip = (v < 2) ? ipa : ipb;
            float4 q = jp[cj];
            float dot = acc[tn][v];
            float ww  = fmaf(ip.y, q.y, -dot);
            float num = fmaf(KCONST, ww, ip.x + q.x);
            float dij = num * ip.z;
            float dji = num * q.z;
            if (__float_as_int(ip.w) == __float_as_int(q.w)) {
                float p1 = dij - 0.01f, p2 = dji - 0.01f;
                if (p1 > 0.f) { ps += p1; pc++; }
                if (p2 > 0.f) { ps += p2; pc++; }
            } else {
                float n1 = 0.2f - dij, n2 = 0.2f - dji;
                if (n1 > 0.f) { ns += n1; nc++; }
                if (n2 > 0.f) { ns += n2; nc++; }
            }
        }
    }

    // ---- block reduce ----
    #pragma unroll
    for (int o = 16; o; o >>= 1) {
        ps += __shfl_xor_sync(0xffffffffu, ps, o);
        ns += __shfl_xor_sync(0xffffffffu, ns, o);
        pc += __shfl_xor_sync(0xffffffffu, pc, o);
        nc += __shfl_xor_sync(0xffffffffu, nc, o);
    }
    __shared__ float rps[32], rns[32];
    __shared__ int   rpc[32], rnc[32];
    if (l == 0) { rps[w] = ps; rns[w] = ns; rpc[w] = pc; rnc[w] = nc; }
    __syncthreads();

    if (t == 0) {
        float PS = 0.f, NS = 0.f; long long PC = 0, NC = 0;
        #pragma unroll
        for (int k = 0; k < 32; k++) { PS += rps[k]; NS += rns[k]; PC += rpc[k]; NC += rnc[k]; }
        atomicAdd(&d_acc.pos_sum, (double)PS);
        atomicAdd(&d_acc.neg_sum, (double)NS);
        atomicAdd(&d_acc.pos_cnt, (unsigned long long)PC);
        atomicAdd(&d_acc.neg_cnt, (unsigned long long)NC);

        __threadfence();
        unsigned old = atomicAdd(&d_acc.done, 1u);
        if (old == NTILES - 1) {
            double psum = __ldcg(&d_acc.pos_sum);
            double nsum = __ldcg(&d_acc.neg_sum);
            double rsum = __ldcg(&d_acc.reg_sum);
            unsigned long long pcnt = __ldcg(&d_acc.pos_cnt);
            unsigned long long ncnt = __ldcg(&d_acc.neg_cnt);
            double pos = psum / ((double)pcnt + 1e-12);
            double neg = nsum / ((double)ncnt + 1e-12);
            double reg = (rsum / (double)NROW) * 0.1;
            out[0] = (float)(pos + neg + reg);
        }
    }
}

// ---------------- launch ----------------
extern "C" void kernel_launch(void* const* d_in, const int* in_sizes, int n_in,
                              void* d_out, int out_size) {
    const float*     embeds = (const float*)d_in[0];
    const long long* labels = (const long long*)d_in[1];

    void* acc_addr = nullptr;
    cudaGetSymbolAddress(&acc_addr, d_acc);

    cudaFuncSetAttribute(pair_kernel, cudaFuncAttributeMaxDynamicSharedMemorySize, SM_TOTAL);

    cudaMemsetAsync(acc_addr, 0, sizeof(Acc));
    precompute_kernel<<<NROW, 256>>>(embeds, labels);
    pair_kernel<<<NTILES, NTHREADS, SM_TOTAL>>>((float*)d_out);
}

// round 11
// speedup vs baseline: 1.1529x; 1.1529x over previous
#include <cuda_runtime.h>
#include <cuda_bf16.h>

#define NROW 8192
#define DIM  256
#define NB   64                  // 128-row blocks
#define NB2  32                  // 256-col super-blocks
#define NTILES2 1056             // sum over bi of (32 - bi/2)
#define CORRF (256.0f/255.0f)
#define KCONST (CORRF/128.0f)
#define HALF_BYTES 32768         // 128 rows x 128 bf16 (256B/row), swizzled
#define HALF_U4 (HALF_BYTES/16)  // 2048
#define NTHREADS 512

// ---------------- scratch ----------------
// per 128-row block b: two contiguous 32KB K-halves at (b*2+h)*32KB
__device__ uint4  d_ebf4[NB * 2 * HALF_U4];
__device__ float4 d_rp[NROW];    // {V, 16*m, 1/V, label bits}

struct Acc {
    double pos_sum, neg_sum, reg_sum;
    unsigned long long pos_cnt, neg_cnt;
    unsigned done;
};
__device__ Acc d_acc;

__device__ __forceinline__ unsigned smem_u32(const void* p) {
    unsigned a;
    asm("{ .reg .u64 t; cvta.to.shared.u64 t, %1; cvt.u32.u64 %0, t; }" : "=r"(a) : "l"(p));
    return a;
}

#define LDSM_X4(r0, r1, r2, r3, a) \
    asm volatile("ldmatrix.sync.aligned.m8n8.x4.shared.b16 {%0,%1,%2,%3}, [%4];" \
        : "=r"(r0), "=r"(r1), "=r"(r2), "=r"(r3) : "r"(a))

#define MMA_BF16(d, a0, a1, a2, a3, b0, b1) \
    asm volatile("mma.sync.aligned.m16n8k16.row.col.f32.bf16.bf16.f32 " \
        "{%0,%1,%2,%3}, {%4,%5,%6,%7}, {%8,%9}, {%0,%1,%2,%3};" \
        : "+f"((d)[0]), "+f"((d)[1]), "+f"((d)[2]), "+f"((d)[3]) \
        : "r"(a0), "r"(a1), "r"(a2), "r"(a3), "r"(b0), "r"(b1))

#define CP16(sdst, gsrc) \
    asm volatile("cp.async.cg.shared.global [%0], [%1], 16;" :: "r"(sdst), "l"(gsrc))
#define CP_COMMIT()  asm volatile("cp.async.commit_group;" ::: "memory")
#define CP_WAIT(n)   asm volatile("cp.async.wait_group %0;" :: "n"(n) : "memory")

// ---------------- precompute: normalize, stats, bf16 swizzled store ----------------
__global__ void precompute_kernel(const float* __restrict__ x,
                                  const long long* __restrict__ lab) {
    int row = blockIdx.x;
    int t = threadIdx.x;                 // feature index, blockDim = 256
    float v = x[row * DIM + t];

    float ss = v * v;
    #pragma unroll
    for (int o = 16; o; o >>= 1) ss += __shfl_xor_sync(0xffffffffu, ss, o);
    __shared__ float red[8];
    if ((t & 31) == 0) red[t >> 5] = ss;
    __syncthreads();
    float tot = red[0] + red[1] + red[2] + red[3] + red[4] + red[5] + red[6] + red[7];

    float norm = sqrtf(tot);
    float e = v / norm;

    __shared__ __nv_bfloat16 sh_e[DIM];
    sh_e[t] = __float2bfloat16(e);

    float s1 = e, s2 = e * e;
    #pragma unroll
    for (int o = 16; o; o >>= 1) {
        s1 += __shfl_xor_sync(0xffffffffu, s1, o);
        s2 += __shfl_xor_sync(0xffffffffu, s2, o);
    }
    __shared__ float red1[8], red2[8];
    if ((t & 31) == 0) { red1[t >> 5] = s1; red2[t >> 5] = s2; }
    __syncthreads();

    if (t < 32) {
        int c = t;                       // global 16B chunk index 0..31
        int k0 = c * 8;
        unsigned w0 = (unsigned)__bfloat16_as_ushort(sh_e[k0 + 0]) | ((unsigned)__bfloat16_as_ushort(sh_e[k0 + 1]) << 16);
        unsigned w1 = (unsigned)__bfloat16_as_ushort(sh_e[k0 + 2]) | ((unsigned)__bfloat16_as_ushort(sh_e[k0 + 3]) << 16);
        unsigned w2 = (unsigned)__bfloat16_as_ushort(sh_e[k0 + 4]) | ((unsigned)__bfloat16_as_ushort(sh_e[k0 + 5]) << 16);
        unsigned w3 = (unsigned)__bfloat16_as_ushort(sh_e[k0 + 6]) | ((unsigned)__bfloat16_as_ushort(sh_e[k0 + 7]) << 16);
        uint4 val; val.x = w0; val.y = w1; val.z = w2; val.w = w3;
        int rb = row & 127;
        int h  = c >> 4;                 // K-half
        int c2 = c & 15;                 // chunk within half (16 per 256B row)
        size_t base = ((size_t)(row >> 7) * 2 + h) * HALF_BYTES;
        unsigned off = (unsigned)rb * 256u + (unsigned)((c2 ^ (rb & 7)) << 4);
        *(uint4*)((char*)d_ebf4 + base + off) = val;
    }

    if (t == 0) {
        float sum_e = 0.f, sum_e2 = 0.f;
        #pragma unroll
        for (int w = 0; w < 8; w++) { sum_e += red1[w]; sum_e2 += red2[w]; }
        float m = sum_e * (1.0f / DIM);
        float s = sum_e2 * (1.0f / DIM);
        float V = CORRF * (s - m * m);
        d_rp[row] = make_float4(V, 16.0f * m, 1.0f / V, __int_as_float((int)lab[row]));
        atomicAdd(&d_acc.reg_sum, (double)fabsf(sum_e));
    }
}

// ---------------- pair kernel: 128x256 tiles, 512 threads, warp = 32x64 ----------------
// dyn smem: [0..4096) j-params (256 x float4),
//           A0 @4096 (32KB), B0 @36864 (64KB), A1 @102400 (32KB), B1 @135168 (64KB)
#define SM_JP 0
#define SM_A0 4096
#define SM_B0 (SM_A0 + 32768)
#define SM_A1 (SM_B0 + 65536)
#define SM_B1 (SM_A1 + 32768)
#define SM_TOTAL (SM_B1 + 65536)

__global__ __launch_bounds__(NTHREADS, 1) void pair_kernel(float* __restrict__ out) {
    // enumerate (bi, bj2): bi 0..63 (128 rows), bj2 >= bi/2 (256 cols)
    int li = blockIdx.x;
    int bi = 0, s = 0;
    while (true) {
        int c = NB2 - (bi >> 1);
        if (li < s + c) break;
        s += c; bi++;
    }
    int bj2 = (bi >> 1) + (li - s);
    // tile is fully upper iff 256*bj2 >= 128*bi + 128  <=>  2*bj2 >= bi+1
    bool partial = (2 * bj2 <= bi);

    extern __shared__ char smem[];
    int t = threadIdx.x, w = t >> 5, l = t & 31;
    int wrow = w & 3;          // M strip: 32 rows
    int wcol = w >> 2;         // N strip: 64 cols
    unsigned sb0 = smem_u32(smem);

    const uint4* Ab  = d_ebf4 + (size_t)(bi * 2) * HALF_U4;           // A block, halves 0/1
    const uint4* Bb0 = d_ebf4 + (size_t)(bj2 * 4) * HALF_U4;          // B rows 0-127
    const uint4* Bb1 = d_ebf4 + (size_t)(bj2 * 4 + 2) * HALF_U4;      // B rows 128-255

    // stage 0: K-half 0
    #pragma unroll
    for (int i = 0; i < 4; i++) CP16(sb0 + SM_A0 + (t + i * NTHREADS) * 16, Ab + t + i * NTHREADS);
    #pragma unroll
    for (int i = 0; i < 4; i++) CP16(sb0 + SM_B0 + (t + i * NTHREADS) * 16, Bb0 + t + i * NTHREADS);
    #pragma unroll
    for (int i = 0; i < 4; i++) CP16(sb0 + SM_B0 + 32768 + (t + i * NTHREADS) * 16, Bb1 + t + i * NTHREADS);
    CP_COMMIT();
    // stage 1: K-half 1
    #pragma unroll
    for (int i = 0; i < 4; i++) CP16(sb0 + SM_A1 + (t + i * NTHREADS) * 16, Ab + HALF_U4 + t + i * NTHREADS);
    #pragma unroll
    for (int i = 0; i < 4; i++) CP16(sb0 + SM_B1 + (t + i * NTHREADS) * 16, Bb0 + HALF_U4 + t + i * NTHREADS);
    #pragma unroll
    for (int i = 0; i < 4; i++) CP16(sb0 + SM_B1 + 32768 + (t + i * NTHREADS) * 16, Bb1 + HALF_U4 + t + i * NTHREADS);
    CP_COMMIT();

    if (t < 256) ((float4*)(smem + SM_JP))[t] = d_rp[bj2 * 256 + t];

    // per-lane ldmatrix addressing
    int rfoff = (l & 7) + (l & 8);   // row-within-16-group
    int hi = l >> 4;                 // chunk parity
    int rA[2], rxA[2];
    #pragma unroll
    for (int mi = 0; mi < 2; mi++) {
        rA[mi] = wrow * 32 + mi * 16 + rfoff;
        rxA[mi] = rA[mi] & 7;
    }
    int rB[4], rxB[4];
    #pragma unroll
    for (int nb = 0; nb < 4; nb++) {
        rB[nb] = wcol * 64 + nb * 16 + rfoff;
        rxB[nb] = rB[nb] & 7;
    }

    float acc[2][8][4];
    #pragma unroll
    for (int mi = 0; mi < 2; mi++)
        #pragma unroll
        for (int tn = 0; tn < 8; tn++)
            #pragma unroll
            for (int j = 0; j < 4; j++) acc[mi][tn][j] = 0.f;

    unsigned aSt[2] = { sb0 + SM_A0, sb0 + SM_A1 };
    unsigned bSt[2] = { sb0 + SM_B0, sb0 + SM_B1 };

    #pragma unroll
    for (int st = 0; st < 2; st++) {
        if (st == 0) CP_WAIT(1); else CP_WAIT(0);
        __syncthreads();
        unsigned aRow[2], bRow[4];
        #pragma unroll
        for (int mi = 0; mi < 2; mi++) aRow[mi] = aSt[st] + (unsigned)rA[mi] * 256u;
        #pragma unroll
        for (int nb = 0; nb < 4; nb++) bRow[nb] = bSt[st] + (unsigned)rB[nb] * 256u;

        #pragma unroll
        for (int ks = 0; ks < 8; ks++) {
            int cc = 2 * ks + hi;
            unsigned a[2][4];
            #pragma unroll
            for (int mi = 0; mi < 2; mi++)
                LDSM_X4(a[mi][0], a[mi][1], a[mi][2], a[mi][3],
                        aRow[mi] + (unsigned)((cc ^ rxA[mi]) << 4));
            #pragma unroll
            for (int nb = 0; nb < 4; nb++) {
                unsigned m0, m1, m2, m3;
                LDSM_X4(m0, m1, m2, m3, bRow[nb] + (unsigned)((cc ^ rxB[nb]) << 4));
                #pragma unroll
                for (int mi = 0; mi < 2; mi++) {
                    MMA_BF16(acc[mi][2 * nb],     a[mi][0], a[mi][1], a[mi][2], a[mi][3], m0, m2);
                    MMA_BF16(acc[mi][2 * nb + 1], a[mi][0], a[mi][1], a[mi][2], a[mi][3], m1, m3);
                }
            }
        }
    }

    // ---- fused epilogue ----
    const float4* jp = (const float4*)(smem + SM_JP);
    int jlo = (l & 3) * 2;
    float ps = 0.f, ns = 0.f;
    int pc = 0, nc = 0;

    #pragma unroll
    for (int mi = 0; mi < 2; mi++) {
        int r0 = wrow * 32 + mi * 16 + (l >> 2);
        int gi0 = bi * 128 + r0;
        float4 ipa = d_rp[gi0];
        float4 ipb = d_rp[gi0 + 8];
        #pragma unroll
        for (int tn = 0; tn < 8; tn++) {
            #pragma unroll
            for (int v = 0; v < 4; v++) {
                int cj = wcol * 64 + tn * 8 + jlo + (v & 1);
                int gi = gi0 + ((v < 2) ? 0 : 8);
                int gj = bj2 * 256 + cj;
                if (partial && gi >= gj) continue;
                float4 ip = (v < 2) ? ipa : ipb;
                float4 q = jp[cj];
                float dot = acc[mi][tn][v];
                float ww  = fmaf(ip.y, q.y, -dot);
                float num = fmaf(KCONST, ww, ip.x + q.x);
                float dij = num * ip.z;
                float dji = num * q.z;
                if (__float_as_int(ip.w) == __float_as_int(q.w)) {
                    float p1 = dij - 0.01f, p2 = dji - 0.01f;
                    if (p1 > 0.f) { ps += p1; pc++; }
                    if (p2 > 0.f) { ps += p2; pc++; }
                } else {
                    float n1 = 0.2f - dij, n2 = 0.2f - dji;
                    if (n1 > 0.f) { ns += n1; nc++; }
                    if (n2 > 0.f) { ns += n2; nc++; }
                }
            }
        }
    }

    // ---- block reduce ----
    #pragma unroll
    for (int o = 16; o; o >>= 1) {
        ps += __shfl_xor_sync(0xffffffffu, ps, o);
        ns += __shfl_xor_sync(0xffffffffu, ns, o);
        pc += __shfl_xor_sync(0xffffffffu, pc, o);
        nc += __shfl_xor_sync(0xffffffffu, nc, o);
    }
    __shared__ float rps[16], rns[16];
    __shared__ int   rpc[16], rnc[16];
    if (l == 0) { rps[w] = ps; rns[w] = ns; rpc[w] = pc; rnc[w] = nc; }
    __syncthreads();

    if (t == 0) {
        float PS = 0.f, NS = 0.f; long long PC = 0, NC = 0;
        #pragma unroll
        for (int k = 0; k < 16; k++) { PS += rps[k]; NS += rns[k]; PC += rpc[k]; NC += rnc[k]; }
        atomicAdd(&d_acc.pos_sum, (double)PS);
        atomicAdd(&d_acc.neg_sum, (double)NS);
        atomicAdd(&d_acc.pos_cnt, (unsigned long long)PC);
        atomicAdd(&d_acc.neg_cnt, (unsigned long long)NC);

        __threadfence();
        unsigned old = atomicAdd(&d_acc.done, 1u);
        if (old == NTILES2 - 1) {
            double psum = __ldcg(&d_acc.pos_sum);
            double nsum = __ldcg(&d_acc.neg_sum);
            double rsum = __ldcg(&d_acc.reg_sum);
            unsigned long long pcnt = __ldcg(&d_acc.pos_cnt);
            unsigned long long ncnt = __ldcg(&d_acc.neg_cnt);
            double pos = psum / ((double)pcnt + 1e-12);
            double neg = nsum / ((double)ncnt + 1e-12);
            double reg = (rsum / (double)NROW) * 0.1;
            out[0] = (float)(pos + neg + reg);
        }
    }
}

// ---------------- launch ----------------
extern "C" void kernel_launch(void* const* d_in, const int* in_sizes, int n_in,
                              void* d_out, int out_size) {
    const float*     embeds = (const float*)d_in[0];
    const long long* labels = (const long long*)d_in[1];

    void* acc_addr = nullptr;
    cudaGetSymbolAddress(&acc_addr, d_acc);

    cudaFuncSetAttribute(pair_kernel, cudaFuncAttributeMaxDynamicSharedMemorySize, SM_TOTAL);

    cudaMemsetAsync(acc_addr, 0, sizeof(Acc));
    precompute_kernel<<<NROW, 256>>>(embeds, labels);
    pair_kernel<<<NTILES2, NTHREADS, SM_TOTAL>>>((float*)d_out);
}